// round 8
// baseline (speedup 1.0000x reference)
#include <cuda_runtime.h>

#define BB 512
#define SS 512
#define CC 96
#define TEAMS 4
#define TEAM_THREADS 192                     // 48 col-pairs x 4 K-quarters
#define FWD_THREADS (TEAMS * TEAM_THREADS)   // 768

typedef unsigned long long u64;

__device__ float g_num[BB];
__device__ float g_den[BB];

// ---- f32x2 packed helpers (sm_103a) ----
__device__ __forceinline__ u64 pack2(float x, float y) {
    u64 r;
    asm("mov.b64 %0, {%1, %2};" : "=l"(r) : "r"(__float_as_int(x)), "r"(__float_as_int(y)));
    return r;
}
__device__ __forceinline__ float2 unpack2(u64 v) {
    int lo, hi;
    asm("mov.b64 {%0, %1}, %2;" : "=r"(lo), "=r"(hi) : "l"(v));
    float2 f; f.x = __int_as_float(lo); f.y = __int_as_float(hi);
    return f;
}
__device__ __forceinline__ void fmadd2(u64& d, u64 a, u64 b) {
    asm("fma.rn.f32x2 %0, %1, %2, %0;" : "+l"(d) : "l"(a), "l"(b));
}
__device__ __forceinline__ u64 add2(u64 a, u64 b) {
    u64 r;
    asm("add.rn.f32x2 %0, %1, %2;" : "=l"(r) : "l"(a), "l"(b));
    return r;
}
__device__ __forceinline__ float fast_rcp(float x) {
    float r;
    asm("rcp.approx.f32 %0, %1;" : "=f"(r) : "f"(x));
    return r;
}

#define TBAR(id) asm volatile("bar.sync %0, %1;" :: "r"(id), "r"(TEAM_THREADS) : "memory")

// =====================================================================
// Forward: 128 CTAs x 768 threads = 4 teams x 192.
// Thread idx: cp = idx>>2 (columns {2cp, 2cp+1}), h = idx&3 (24-state
// K-quarter). 6 LDS.128 feed 24 FFMA2. Reduction: shfl.xor(1) swaps
// column partials, shfl.xor(2) merges state halves; every thread ends
// with the full sum for column col = 2cp + (h&1) (h and h^2 duplicate
// with identical values — benign).
// Unnormalized exp domain; r = rcp(u_prev[0]) computed locally; exact
// shift tracking S -= log(r) on thread 0. One barrier/step, ping-pong.
// =====================================================================
__global__ __launch_bounds__(FWD_THREADS, 1) void crf_forward_kernel(
    const float* __restrict__ em,
    const int* __restrict__ masks,
    const float* __restrict__ start,
    const float* __restrict__ endt,
    const float* __restrict__ trans)
{
    const int team = threadIdx.x / TEAM_THREADS;
    const int idx  = threadIdx.x - team * TEAM_THREADS;   // 0..191
    const int cp = idx >> 2;
    const int h  = idx & 3;
    const int col = 2 * cp + (h & 1);
    const int barid = team + 1;
    const int b = blockIdx.x * TEAMS + team;

    __shared__ __align__(16) float s_u[2][TEAMS][CC];

    // expT rows [24h, 24h+24) for columns 2cp, 2cp+1, packed in state pairs.
    u64 cA[12], cB[12];
    const int colA = 2 * cp, colB = 2 * cp + 1;
#pragma unroll
    for (int m = 0; m < 12; m++) {
        int row = 24 * h + 2 * m;
        cA[m] = pack2(__expf(trans[row * CC + colA]), __expf(trans[(row + 1) * CC + colA]));
        cB[m] = pack2(__expf(trans[row * CC + colB]), __expf(trans[(row + 1) * CC + colB]));
    }

    const float* emb = em + (size_t)b * SS * CC + col;
    const int* mb = masks + (size_t)b * SS;

    // ---- t = 0 ----
    float u = __expf(start[col] + emb[0]);
    float S = 0.f;
    s_u[0][team][col] = u;

    // prefetch pipeline (distance 2)
    float E = __expf(emb[1 * CC]);
    int m_cur = mb[1];
    float em_next = emb[2 * CC];
    int m_next = mb[2];
    TBAR(barid);

    int p = 0;
    for (int t = 1; t < SS; t++) {
        float r = fast_rcp(s_u[p][team][0]);

        int pf = t + 2 < SS ? t + 2 : SS - 1;
        float em_pf = emb[pf * CC];
        int m_pf = mb[pf];

        // partial matvec: 24 states (quarter h) x 2 columns
        const ulonglong2* pv = reinterpret_cast<const ulonglong2*>(&s_u[p][team][24 * h]);
        u64 qA0 = 0ull, qA1 = 0ull, qB0 = 0ull, qB1 = 0ull;
#pragma unroll
        for (int k = 0; k < 6; k++) {
            ulonglong2 pp = pv[k];
            fmadd2(qA0, pp.x, cA[2 * k]);
            fmadd2(qA1, pp.y, cA[2 * k + 1]);
            fmadd2(qB0, pp.x, cB[2 * k]);
            fmadd2(qB1, pp.y, cB[2 * k + 1]);
        }
        float2 fa = unpack2(add2(qA0, qA1));
        float2 fb = unpack2(add2(qB0, qB1));
        float wA = fa.x + fa.y;
        float wB = fb.x + fb.y;

        // reduce over the 4 K-quarters; finalize column col = 2cp+(h&1)
        float mine  = (h & 1) ? wB : wA;
        float other = (h & 1) ? wA : wB;
        float v1 = mine + __shfl_xor_sync(0xFFFFFFFFu, other, 1);
        float q  = v1 + __shfl_xor_sync(0xFFFFFFFFu, v1, 2);

        float u_new = q * (E * r);
        u = m_cur ? u_new : u;
        s_u[p ^ 1][team][col] = u;
        if (idx == 0) S = m_cur ? S - __logf(r) : S;

        // rotate prefetch
        E = __expf(em_next);
        m_cur = m_next;
        em_next = em_pf;
        m_next = m_pf;

        TBAR(barid);
        p ^= 1;
    }

    // denominator = S + log(sum_j u_j * exp(end_j))
    s_u[p][team][col] = u * __expf(endt[col]);
    TBAR(barid);
    if (idx == 0) {
        float s = 0.f;
#pragma unroll
        for (int i = 0; i < CC; i++) s += s_u[p][team][i];
        g_den[b] = S + __logf(s);
    }
}

// =====================================================================
// Numerator: one CTA (128 threads) per batch.
// =====================================================================
__global__ __launch_bounds__(128) void crf_num_kernel(
    const float* __restrict__ em,
    const int* __restrict__ tags,
    const int* __restrict__ masks,
    const float* __restrict__ start,
    const float* __restrict__ endt,
    const float* __restrict__ trans)
{
    const int b = blockIdx.x;
    const int tid = threadIdx.x;
    const int* tg = tags + (size_t)b * SS;
    const int* mk = masks + (size_t)b * SS;
    const float* e = em + (size_t)b * SS * CC;

    float s = 0.f;
    int cnt = 0;
#pragma unroll
    for (int it = 0; it < SS / 128; it++) {
        int t = tid + it * 128;
        int tagt = tg[t];
        int m = mk[t];
        cnt += m ? 1 : 0;
        if (t == 0) {
            s += start[tagt] + e[tagt];
        } else if (m) {
            int tp = tg[t - 1];
            s += trans[tp * CC + tagt] + e[(size_t)t * CC + tagt];
        }
    }
    __shared__ float ss[4];
    __shared__ int sc[4];
#pragma unroll
    for (int o = 16; o; o >>= 1) {
        s += __shfl_xor_sync(0xFFFFFFFFu, s, o);
        cnt += __shfl_xor_sync(0xFFFFFFFFu, cnt, o);
    }
    int w = tid >> 5, lane = tid & 31;
    if (lane == 0) { ss[w] = s; sc[w] = cnt; }
    __syncthreads();
    if (tid == 0) {
        float st = ss[0] + ss[1] + ss[2] + ss[3];
        int ct = sc[0] + sc[1] + sc[2] + sc[3];
        int lt = tg[ct - 1];
        g_num[b] = st + endt[lt];
    }
}

// =====================================================================
// Final mean reduce
// =====================================================================
__global__ void crf_reduce_kernel(float* __restrict__ out)
{
    __shared__ float sh[BB];
    int t = threadIdx.x;
    sh[t] = g_num[t] - g_den[t];
    __syncthreads();
#pragma unroll
    for (int o = BB / 2; o > 0; o >>= 1) {
        if (t < o) sh[t] += sh[t + o];
        __syncthreads();
    }
    if (t == 0) out[0] = sh[0] * (1.0f / (float)BB);
}

extern "C" void kernel_launch(void* const* d_in, const int* in_sizes, int n_in,
                              void* d_out, int out_size)
{
    const float* em    = (const float*)d_in[0];
    const int*   tags  = (const int*)d_in[1];
    const int*   masks = (const int*)d_in[2];
    const float* start = (const float*)d_in[3];
    const float* endt  = (const float*)d_in[4];
    const float* trans = (const float*)d_in[5];
    float* out = (float*)d_out;

    crf_forward_kernel<<<BB / TEAMS, FWD_THREADS>>>(em, masks, start, endt, trans);
    crf_num_kernel<<<BB, 128>>>(em, tags, masks, start, endt, trans);
    crf_reduce_kernel<<<1, BB>>>(out);
}

// round 9
// speedup vs baseline: 1.0633x; 1.0633x over previous
#include <cuda_runtime.h>

#define BB 512
#define SS 512
#define CC 96
#define TEAMS 4
#define TEAM_THREADS 192                     // 6 warps: (cb 0..2) x (h 0..1)
#define FWD_THREADS (TEAMS * TEAM_THREADS)   // 768

typedef unsigned long long u64;

__device__ float g_num[BB];
__device__ float g_den[BB];

// ---- f32x2 packed helpers (sm_103a) ----
__device__ __forceinline__ u64 pack2(float x, float y) {
    u64 r;
    asm("mov.b64 %0, {%1, %2};" : "=l"(r) : "r"(__float_as_int(x)), "r"(__float_as_int(y)));
    return r;
}
__device__ __forceinline__ float2 unpack2(u64 v) {
    int lo, hi;
    asm("mov.b64 {%0, %1}, %2;" : "=r"(lo), "=r"(hi) : "l"(v));
    float2 f; f.x = __int_as_float(lo); f.y = __int_as_float(hi);
    return f;
}
__device__ __forceinline__ void fmadd2(u64& d, u64 a, u64 b) {
    asm("fma.rn.f32x2 %0, %1, %2, %0;" : "+l"(d) : "l"(a), "l"(b));
}
__device__ __forceinline__ u64 add2(u64 a, u64 b) {
    u64 r;
    asm("add.rn.f32x2 %0, %1, %2;" : "=l"(r) : "l"(a), "l"(b));
    return r;
}
__device__ __forceinline__ float fast_rcp(float x) {
    float r;
    asm("rcp.approx.f32 %0, %1;" : "=f"(r) : "f"(x));
    return r;
}

#define BARN(id, cnt) asm volatile("bar.sync %0, %1;" :: "r"(id), "r"(cnt) : "memory")

// =====================================================================
// Forward: 128 CTAs x 768 threads = 4 teams x 6 warps.
// Warp w in team: h = w&1 (K-half, WARP-UNIFORM -> every LDS.128 of the
// u vector is a single-address broadcast, 1 crossbar phase), cb = w>>1.
// Lane owns column col = 32*cb + lane; 24 u64 coefficients in regs.
// Cross-half combine via smem partials + 64-thread pair barrier;
// h=0 warps run the epilogue (normalize, mask, store u), h=1 idle to
// the team barrier. Unnormalized exp domain, r = rcp(u_prev[0]),
// exact shift tracking S -= log(r) on thread 0.
// =====================================================================
__global__ __launch_bounds__(FWD_THREADS, 1) void crf_forward_kernel(
    const float* __restrict__ em,
    const int* __restrict__ masks,
    const float* __restrict__ start,
    const float* __restrict__ endt,
    const float* __restrict__ trans)
{
    const int team = threadIdx.x / TEAM_THREADS;
    const int idx  = threadIdx.x - team * TEAM_THREADS;   // 0..191
    const int w    = idx >> 5;          // warp in team, 0..5
    const int lane = idx & 31;
    const int h    = w & 1;             // K-half (warp-uniform)
    const int cb   = w >> 1;            // column block 0..2
    const int col  = 32 * cb + lane;
    const int b    = blockIdx.x * TEAMS + team;
    const int team_bar = team;                 // ids 0..3, 192 threads
    const int pair_bar = 4 + team * 3 + cb;    // ids 4..15, 64 threads

    __shared__ __align__(16) float s_u[2][TEAMS][CC];
    __shared__ float s_w[TEAMS][2][CC];

    // expT rows [48h, 48h+48) of column col, packed over state pairs.
    u64 c[24];
#pragma unroll
    for (int m = 0; m < 24; m++) {
        int row = 48 * h + 2 * m;
        c[m] = pack2(__expf(trans[row * CC + col]), __expf(trans[(row + 1) * CC + col]));
    }

    const float* emb = em + (size_t)b * SS * CC + col;
    const int* mb = masks + (size_t)b * SS;

    // ---- t = 0 + prefetch (h=0 warps only own per-column state) ----
    float u = 0.f, S = 0.f;
    float E = 0.f, em_next = 0.f;
    int m_cur = 0, m_next = 0;
    if (h == 0) {
        u = __expf(start[col] + emb[0]);
        s_u[0][team][col] = u;
        E = __expf(emb[1 * CC]);
        m_cur = mb[1];
        em_next = emb[2 * CC];
        m_next = mb[2];
    }
    BARN(team_bar, TEAM_THREADS);

    int p = 0;
    for (int t = 1; t < SS; t++) {
        // partial matvec over my 48 states: single-address broadcast LDS
        const ulonglong2* pv = reinterpret_cast<const ulonglong2*>(&s_u[p][team][48 * h]);
        u64 q0 = 0ull, q1 = 0ull, q2 = 0ull, q3 = 0ull;
#pragma unroll
        for (int k = 0; k < 6; k++) {
            ulonglong2 pa = pv[2 * k];
            ulonglong2 pb = pv[2 * k + 1];
            fmadd2(q0, pa.x, c[4 * k]);
            fmadd2(q1, pa.y, c[4 * k + 1]);
            fmadd2(q2, pb.x, c[4 * k + 2]);
            fmadd2(q3, pb.y, c[4 * k + 3]);
        }
        float2 f = unpack2(add2(add2(q0, q1), add2(q2, q3)));
        s_w[team][h][col] = f.x + f.y;
        BARN(pair_bar, 64);

        if (h == 0) {
            float r = fast_rcp(s_u[p][team][0]);
            float q = s_w[team][0][col] + s_w[team][1][col];

            int pf = t + 2 < SS ? t + 2 : SS - 1;
            float em_pf = emb[pf * CC];
            int m_pf = mb[pf];

            float u_new = q * (E * r);
            u = m_cur ? u_new : u;
            s_u[p ^ 1][team][col] = u;
            if (idx == 0) S = m_cur ? S - __logf(r) : S;

            E = __expf(em_next);
            m_cur = m_next;
            em_next = em_pf;
            m_next = m_pf;
        }
        BARN(team_bar, TEAM_THREADS);
        p ^= 1;
    }

    // denominator = S + log(sum_j u_j * exp(end_j))
    if (h == 0) s_u[p][team][col] = u * __expf(endt[col]);
    BARN(team_bar, TEAM_THREADS);
    if (idx == 0) {
        float s = 0.f;
#pragma unroll
        for (int i = 0; i < CC; i++) s += s_u[p][team][i];
        g_den[b] = S + __logf(s);
    }
}

// =====================================================================
// Numerator: one CTA (128 threads) per batch.
// =====================================================================
__global__ __launch_bounds__(128) void crf_num_kernel(
    const float* __restrict__ em,
    const int* __restrict__ tags,
    const int* __restrict__ masks,
    const float* __restrict__ start,
    const float* __restrict__ endt,
    const float* __restrict__ trans)
{
    const int b = blockIdx.x;
    const int tid = threadIdx.x;
    const int* tg = tags + (size_t)b * SS;
    const int* mk = masks + (size_t)b * SS;
    const float* e = em + (size_t)b * SS * CC;

    float s = 0.f;
    int cnt = 0;
#pragma unroll
    for (int it = 0; it < SS / 128; it++) {
        int t = tid + it * 128;
        int tagt = tg[t];
        int m = mk[t];
        cnt += m ? 1 : 0;
        if (t == 0) {
            s += start[tagt] + e[tagt];
        } else if (m) {
            int tp = tg[t - 1];
            s += trans[tp * CC + tagt] + e[(size_t)t * CC + tagt];
        }
    }
    __shared__ float ss[4];
    __shared__ int sc[4];
#pragma unroll
    for (int o = 16; o; o >>= 1) {
        s += __shfl_xor_sync(0xFFFFFFFFu, s, o);
        cnt += __shfl_xor_sync(0xFFFFFFFFu, cnt, o);
    }
    int wv = tid >> 5, lane = tid & 31;
    if (lane == 0) { ss[wv] = s; sc[wv] = cnt; }
    __syncthreads();
    if (tid == 0) {
        float st = ss[0] + ss[1] + ss[2] + ss[3];
        int ct = sc[0] + sc[1] + sc[2] + sc[3];
        int lt = tg[ct - 1];
        g_num[b] = st + endt[lt];
    }
}

// =====================================================================
// Final mean reduce
// =====================================================================
__global__ void crf_reduce_kernel(float* __restrict__ out)
{
    __shared__ float sh[BB];
    int t = threadIdx.x;
    sh[t] = g_num[t] - g_den[t];
    __syncthreads();
#pragma unroll
    for (int o = BB / 2; o > 0; o >>= 1) {
        if (t < o) sh[t] += sh[t + o];
        __syncthreads();
    }
    if (t == 0) out[0] = sh[0] * (1.0f / (float)BB);
}

extern "C" void kernel_launch(void* const* d_in, const int* in_sizes, int n_in,
                              void* d_out, int out_size)
{
    const float* em    = (const float*)d_in[0];
    const int*   tags  = (const int*)d_in[1];
    const int*   masks = (const int*)d_in[2];
    const float* start = (const float*)d_in[3];
    const float* endt  = (const float*)d_in[4];
    const float* trans = (const float*)d_in[5];
    float* out = (float*)d_out;

    crf_forward_kernel<<<BB / TEAMS, FWD_THREADS>>>(em, masks, start, endt, trans);
    crf_num_kernel<<<BB, 128>>>(em, tags, masks, start, endt, trans);
    crf_reduce_kernel<<<1, BB>>>(out);
}

// round 10
// speedup vs baseline: 1.0647x; 1.0013x over previous
#include <cuda_runtime.h>

#define BB 512
#define SS 512
#define CC 96
#define TEAMS 4
#define TEAM_THREADS 192                     // 6 warps: (cb 0..2) x (h 0..1)
#define FWD_THREADS (TEAMS * TEAM_THREADS)   // 768

typedef unsigned long long u64;

__device__ float g_num[BB];
__device__ float g_den[BB];

// ---- f32x2 packed helpers (sm_103a) ----
__device__ __forceinline__ u64 pack2(float x, float y) {
    u64 r;
    asm("mov.b64 %0, {%1, %2};" : "=l"(r) : "r"(__float_as_int(x)), "r"(__float_as_int(y)));
    return r;
}
__device__ __forceinline__ float2 unpack2(u64 v) {
    int lo, hi;
    asm("mov.b64 {%0, %1}, %2;" : "=r"(lo), "=r"(hi) : "l"(v));
    float2 f; f.x = __int_as_float(lo); f.y = __int_as_float(hi);
    return f;
}
__device__ __forceinline__ void fmadd2(u64& d, u64 a, u64 b) {
    asm("fma.rn.f32x2 %0, %1, %2, %0;" : "+l"(d) : "l"(a), "l"(b));
}
__device__ __forceinline__ u64 add2(u64 a, u64 b) {
    u64 r;
    asm("add.rn.f32x2 %0, %1, %2;" : "=l"(r) : "l"(a), "l"(b));
    return r;
}
__device__ __forceinline__ float fast_rcp(float x) {
    float r;
    asm("rcp.approx.f32 %0, %1;" : "=f"(r) : "f"(x));
    return r;
}

#define BARN(id, cnt) asm volatile("bar.sync %0, %1;" :: "r"(id), "r"(cnt) : "memory")

// =====================================================================
// Forward: 128 CTAs x 768 threads = 4 teams x 6 warps.
// Warp w in team: h = w&1 (K-half, WARP-UNIFORM -> every LDS.128 of the
// u vector is a single-address broadcast, 1 crossbar phase), cb = w>>1.
// Lane owns column col = 32*cb + lane; 24 u64 coefficients in regs.
// Cross-half combine via smem partials + 64-thread pair barrier;
// h=0 warps run the epilogue (normalize, mask, store u), h=1 idle to
// the team barrier. Unnormalized exp domain, r = rcp(u_prev[0]),
// exact shift tracking S -= log(r) on thread 0.
// =====================================================================
__global__ __launch_bounds__(FWD_THREADS, 1) void crf_forward_kernel(
    const float* __restrict__ em,
    const int* __restrict__ masks,
    const float* __restrict__ start,
    const float* __restrict__ endt,
    const float* __restrict__ trans)
{
    const int team = threadIdx.x / TEAM_THREADS;
    const int idx  = threadIdx.x - team * TEAM_THREADS;   // 0..191
    const int w    = idx >> 5;          // warp in team, 0..5
    const int lane = idx & 31;
    const int h    = w & 1;             // K-half (warp-uniform)
    const int cb   = w >> 1;            // column block 0..2
    const int col  = 32 * cb + lane;
    const int b    = blockIdx.x * TEAMS + team;
    const int team_bar = team;                 // ids 0..3, 192 threads
    const int pair_bar = 4 + team * 3 + cb;    // ids 4..15, 64 threads

    __shared__ __align__(16) float s_u[2][TEAMS][CC];
    __shared__ float s_w[TEAMS][2][CC];

    // expT rows [48h, 48h+48) of column col, packed over state pairs.
    u64 c[24];
#pragma unroll
    for (int m = 0; m < 24; m++) {
        int row = 48 * h + 2 * m;
        c[m] = pack2(__expf(trans[row * CC + col]), __expf(trans[(row + 1) * CC + col]));
    }

    const float* emb = em + (size_t)b * SS * CC + col;
    const int* mb = masks + (size_t)b * SS;

    // ---- t = 0 + prefetch (h=0 warps only own per-column state) ----
    float u = 0.f, S = 0.f;
    float E = 0.f, em_next = 0.f;
    int m_cur = 0, m_next = 0;
    if (h == 0) {
        u = __expf(start[col] + emb[0]);
        s_u[0][team][col] = u;
        E = __expf(emb[1 * CC]);
        m_cur = mb[1];
        em_next = emb[2 * CC];
        m_next = mb[2];
    }
    BARN(team_bar, TEAM_THREADS);

    int p = 0;
    for (int t = 1; t < SS; t++) {
        // partial matvec over my 48 states: single-address broadcast LDS
        const ulonglong2* pv = reinterpret_cast<const ulonglong2*>(&s_u[p][team][48 * h]);
        u64 q0 = 0ull, q1 = 0ull, q2 = 0ull, q3 = 0ull;
#pragma unroll
        for (int k = 0; k < 6; k++) {
            ulonglong2 pa = pv[2 * k];
            ulonglong2 pb = pv[2 * k + 1];
            fmadd2(q0, pa.x, c[4 * k]);
            fmadd2(q1, pa.y, c[4 * k + 1]);
            fmadd2(q2, pb.x, c[4 * k + 2]);
            fmadd2(q3, pb.y, c[4 * k + 3]);
        }
        float2 f = unpack2(add2(add2(q0, q1), add2(q2, q3)));
        s_w[team][h][col] = f.x + f.y;
        BARN(pair_bar, 64);

        if (h == 0) {
            float r = fast_rcp(s_u[p][team][0]);
            float q = s_w[team][0][col] + s_w[team][1][col];

            int pf = t + 2 < SS ? t + 2 : SS - 1;
            float em_pf = emb[pf * CC];
            int m_pf = mb[pf];

            float u_new = q * (E * r);
            u = m_cur ? u_new : u;
            s_u[p ^ 1][team][col] = u;
            if (idx == 0) S = m_cur ? S - __logf(r) : S;

            E = __expf(em_next);
            m_cur = m_next;
            em_next = em_pf;
            m_next = m_pf;
        }
        BARN(team_bar, TEAM_THREADS);
        p ^= 1;
    }

    // denominator = S + log(sum_j u_j * exp(end_j))
    if (h == 0) s_u[p][team][col] = u * __expf(endt[col]);
    BARN(team_bar, TEAM_THREADS);
    if (idx == 0) {
        float s = 0.f;
#pragma unroll
        for (int i = 0; i < CC; i++) s += s_u[p][team][i];
        g_den[b] = S + __logf(s);
    }
}

// =====================================================================
// Numerator: one CTA (128 threads) per batch.
// =====================================================================
__global__ __launch_bounds__(128) void crf_num_kernel(
    const float* __restrict__ em,
    const int* __restrict__ tags,
    const int* __restrict__ masks,
    const float* __restrict__ start,
    const float* __restrict__ endt,
    const float* __restrict__ trans)
{
    const int b = blockIdx.x;
    const int tid = threadIdx.x;
    const int* tg = tags + (size_t)b * SS;
    const int* mk = masks + (size_t)b * SS;
    const float* e = em + (size_t)b * SS * CC;

    float s = 0.f;
    int cnt = 0;
#pragma unroll
    for (int it = 0; it < SS / 128; it++) {
        int t = tid + it * 128;
        int tagt = tg[t];
        int m = mk[t];
        cnt += m ? 1 : 0;
        if (t == 0) {
            s += start[tagt] + e[tagt];
        } else if (m) {
            int tp = tg[t - 1];
            s += trans[tp * CC + tagt] + e[(size_t)t * CC + tagt];
        }
    }
    __shared__ float ss[4];
    __shared__ int sc[4];
#pragma unroll
    for (int o = 16; o; o >>= 1) {
        s += __shfl_xor_sync(0xFFFFFFFFu, s, o);
        cnt += __shfl_xor_sync(0xFFFFFFFFu, cnt, o);
    }
    int wv = tid >> 5, lane = tid & 31;
    if (lane == 0) { ss[wv] = s; sc[wv] = cnt; }
    __syncthreads();
    if (tid == 0) {
        float st = ss[0] + ss[1] + ss[2] + ss[3];
        int ct = sc[0] + sc[1] + sc[2] + sc[3];
        int lt = tg[ct - 1];
        g_num[b] = st + endt[lt];
    }
}

// =====================================================================
// Final mean reduce
// =====================================================================
__global__ void crf_reduce_kernel(float* __restrict__ out)
{
    __shared__ float sh[BB];
    int t = threadIdx.x;
    sh[t] = g_num[t] - g_den[t];
    __syncthreads();
#pragma unroll
    for (int o = BB / 2; o > 0; o >>= 1) {
        if (t < o) sh[t] += sh[t + o];
        __syncthreads();
    }
    if (t == 0) out[0] = sh[0] * (1.0f / (float)BB);
}

extern "C" void kernel_launch(void* const* d_in, const int* in_sizes, int n_in,
                              void* d_out, int out_size)
{
    const float* em    = (const float*)d_in[0];
    const int*   tags  = (const int*)d_in[1];
    const int*   masks = (const int*)d_in[2];
    const float* start = (const float*)d_in[3];
    const float* endt  = (const float*)d_in[4];
    const float* trans = (const float*)d_in[5];
    float* out = (float*)d_out;

    crf_forward_kernel<<<BB / TEAMS, FWD_THREADS>>>(em, masks, start, endt, trans);
    crf_num_kernel<<<BB, 128>>>(em, tags, masks, start, endt, trans);
    crf_reduce_kernel<<<1, BB>>>(out);
}

// round 11
// speedup vs baseline: 1.6575x; 1.5568x over previous
#include <cuda_runtime.h>

#define BB 512
#define SS 512
#define CC 96
#define TEAMS 4
#define TEAM_THREADS 64                      // 32 col-triples x 2 K-halves
#define FWD_THREADS (TEAMS * TEAM_THREADS)   // 256

typedef unsigned long long u64;

__device__ float g_num[BB];
__device__ float g_den[BB];

// ---- f32x2 packed helpers (sm_103a) ----
__device__ __forceinline__ u64 pack2(float x, float y) {
    u64 r;
    asm("mov.b64 %0, {%1, %2};" : "=l"(r) : "r"(__float_as_int(x)), "r"(__float_as_int(y)));
    return r;
}
__device__ __forceinline__ float2 unpack2(u64 v) {
    int lo, hi;
    asm("mov.b64 {%0, %1}, %2;" : "=r"(lo), "=r"(hi) : "l"(v));
    float2 f; f.x = __int_as_float(lo); f.y = __int_as_float(hi);
    return f;
}
__device__ __forceinline__ void fmadd2(u64& d, u64 a, u64 b) {
    asm("fma.rn.f32x2 %0, %1, %2, %0;" : "+l"(d) : "l"(a), "l"(b));
}
__device__ __forceinline__ u64 add2(u64 a, u64 b) {
    u64 r;
    asm("add.rn.f32x2 %0, %1, %2;" : "=l"(r) : "l"(a), "l"(b));
    return r;
}
__device__ __forceinline__ float fast_rcp(float x) {
    float r;
    asm("rcp.approx.f32 %0, %1;" : "=f"(r) : "f"(x));
    return r;
}

#define BARN(id, cnt) asm volatile("bar.sync %0, %1;" :: "r"(id), "r"(cnt) : "memory")

// =====================================================================
// Forward: 128 CTAs x 256 threads = 4 teams x 64 (2 warps each, 8
// warps/CTA -> exactly 2/SMSP, independent teams per SMSP).
// Thread idx: cp = idx>>1 owns columns {3cp,3cp+1,3cp+2}; h = idx&1 is
// the 48-state K-half. 12 LDS.128 (2-phase) feed 72 FFMA2 in 6 chains.
// Combine: 3x shfl.xor(1). h=0 finalizes cols c0,c2; h=1 finalizes c1.
// Unnormalized exp domain; normalizer r published pre-reciprocated in
// ping-ponged s_r by the col-0 owner; exact shift S -= log(r).
// One team barrier per step.
// =====================================================================
__global__ __launch_bounds__(FWD_THREADS, 1) void crf_forward_kernel(
    const float* __restrict__ em,
    const int* __restrict__ masks,
    const float* __restrict__ start,
    const float* __restrict__ endt,
    const float* __restrict__ trans)
{
    const int team = threadIdx.x / TEAM_THREADS;
    const int idx  = threadIdx.x - team * TEAM_THREADS;   // 0..63
    const int cp = idx >> 1;
    const int h  = idx & 1;
    const int c0 = 3 * cp, c1 = 3 * cp + 1, c2 = 3 * cp + 2;
    const int b  = blockIdx.x * TEAMS + team;

    __shared__ __align__(16) float s_u[2][TEAMS][CC];
    __shared__ float s_r[2][TEAMS];

    // Coefficients: expT rows [48h, 48h+48) for the 3 owned columns,
    // packed over state pairs. 72 u64 in registers.
    u64 cA[24], cB[24], cCk[24];
#pragma unroll
    for (int m = 0; m < 24; m++) {
        int row = 48 * h + 2 * m;
        const float* r0 = trans + row * CC;
        const float* r1 = trans + (row + 1) * CC;
        cA[m]  = pack2(__expf(r0[c0]), __expf(r1[c0]));
        cB[m]  = pack2(__expf(r0[c1]), __expf(r1[c1]));
        cCk[m] = pack2(__expf(r0[c2]), __expf(r1[c2]));
    }

    const float* emb = em + (size_t)b * SS * CC;
    const int* mb = masks + (size_t)b * SS;

    // My finalized columns: slot0 always; slot1 only for h==0.
    const int my0 = h ? c1 : c0;
    const int my1 = c2;   // used when h==0

    // ---- t = 0 ----
    float u0 = __expf(start[my0] + emb[my0]);
    float u1 = 0.f;
    s_u[0][team][my0] = u0;
    if (h == 0) {
        u1 = __expf(start[my1] + emb[my1]);
        s_u[0][team][my1] = u1;
    }
    float S = 0.f;
    if (idx == 0) s_r[0][team] = fast_rcp(u0);   // col 0 owner

    // prefetch pipeline (distance 2)
    float E0 = __expf(emb[1 * CC + my0]);
    float en0 = emb[2 * CC + my0];
    float E1 = 0.f, en1 = 0.f;
    if (h == 0) {
        E1 = __expf(emb[1 * CC + my1]);
        en1 = emb[2 * CC + my1];
    }
    int m_cur = mb[1];
    int m_next = mb[2];
    BARN(team, TEAM_THREADS);

    int p = 0;
    for (int t = 1; t < SS; t++) {
        float r = s_r[p][team];

        int pf = t + 2 < SS ? t + 2 : SS - 1;
        float ep0 = emb[(size_t)pf * CC + my0];
        float ep1 = 0.f;
        if (h == 0) ep1 = emb[(size_t)pf * CC + my1];
        int m_pf = mb[pf];

        // partial matvec: 48 states (half h) x 3 columns
        const ulonglong2* pv = reinterpret_cast<const ulonglong2*>(&s_u[p][team][48 * h]);
        u64 qa0 = 0ull, qa1 = 0ull, qb0 = 0ull, qb1 = 0ull, qc0 = 0ull, qc1 = 0ull;
#pragma unroll
        for (int k = 0; k < 12; k++) {
            ulonglong2 pp = pv[k];
            fmadd2(qa0, pp.x, cA[2 * k]);
            fmadd2(qa1, pp.y, cA[2 * k + 1]);
            fmadd2(qb0, pp.x, cB[2 * k]);
            fmadd2(qb1, pp.y, cB[2 * k + 1]);
            fmadd2(qc0, pp.x, cCk[2 * k]);
            fmadd2(qc1, pp.y, cCk[2 * k + 1]);
        }
        float2 fa = unpack2(add2(qa0, qa1));
        float2 fb = unpack2(add2(qb0, qb1));
        float2 fc = unpack2(add2(qc0, qc1));
        float wA = fa.x + fa.y;
        float wB = fb.x + fb.y;
        float wC = fc.x + fc.y;

        // combine K-halves with the lane partner
        float qA = wA + __shfl_xor_sync(0xFFFFFFFFu, wA, 1);
        float qB = wB + __shfl_xor_sync(0xFFFFFFFFu, wB, 1);
        float qC = wC + __shfl_xor_sync(0xFFFFFFFFu, wC, 1);

        // finalize my columns
        float q0 = h ? qB : qA;
        float un0 = q0 * (E0 * r);
        u0 = m_cur ? un0 : u0;
        s_u[p ^ 1][team][my0] = u0;
        if (h == 0) {
            float un1 = qC * (E1 * r);
            u1 = m_cur ? un1 : u1;
            s_u[p ^ 1][team][my1] = u1;
        }
        if (idx == 0) {
            s_r[p ^ 1][team] = fast_rcp(u0);
            S = m_cur ? S - __logf(r) : S;
        }

        // rotate prefetch
        E0 = __expf(en0);
        en0 = ep0;
        if (h == 0) {
            E1 = __expf(en1);
            en1 = ep1;
        }
        m_cur = m_next;
        m_next = m_pf;

        BARN(team, TEAM_THREADS);
        p ^= 1;
    }

    // denominator = S + log(sum_j u_j * exp(end_j))
    s_u[p][team][my0] = u0 * __expf(endt[my0]);
    if (h == 0) s_u[p][team][my1] = u1 * __expf(endt[my1]);
    BARN(team, TEAM_THREADS);
    if (idx == 0) {
        float s = 0.f;
#pragma unroll
        for (int i = 0; i < CC; i++) s += s_u[p][team][i];
        g_den[b] = S + __logf(s);
    }
}

// =====================================================================
// Numerator: one CTA (128 threads) per batch.
// =====================================================================
__global__ __launch_bounds__(128) void crf_num_kernel(
    const float* __restrict__ em,
    const int* __restrict__ tags,
    const int* __restrict__ masks,
    const float* __restrict__ start,
    const float* __restrict__ endt,
    const float* __restrict__ trans)
{
    const int b = blockIdx.x;
    const int tid = threadIdx.x;
    const int* tg = tags + (size_t)b * SS;
    const int* mk = masks + (size_t)b * SS;
    const float* e = em + (size_t)b * SS * CC;

    float s = 0.f;
    int cnt = 0;
#pragma unroll
    for (int it = 0; it < SS / 128; it++) {
        int t = tid + it * 128;
        int tagt = tg[t];
        int m = mk[t];
        cnt += m ? 1 : 0;
        if (t == 0) {
            s += start[tagt] + e[tagt];
        } else if (m) {
            int tp = tg[t - 1];
            s += trans[tp * CC + tagt] + e[(size_t)t * CC + tagt];
        }
    }
    __shared__ float ss[4];
    __shared__ int sc[4];
#pragma unroll
    for (int o = 16; o; o >>= 1) {
        s += __shfl_xor_sync(0xFFFFFFFFu, s, o);
        cnt += __shfl_xor_sync(0xFFFFFFFFu, cnt, o);
    }
    int wv = tid >> 5, lane = tid & 31;
    if (lane == 0) { ss[wv] = s; sc[wv] = cnt; }
    __syncthreads();
    if (tid == 0) {
        float st = ss[0] + ss[1] + ss[2] + ss[3];
        int ct = sc[0] + sc[1] + sc[2] + sc[3];
        int lt = tg[ct - 1];
        g_num[b] = st + endt[lt];
    }
}

// =====================================================================
// Final mean reduce
// =====================================================================
__global__ void crf_reduce_kernel(float* __restrict__ out)
{
    __shared__ float sh[BB];
    int t = threadIdx.x;
    sh[t] = g_num[t] - g_den[t];
    __syncthreads();
#pragma unroll
    for (int o = BB / 2; o > 0; o >>= 1) {
        if (t < o) sh[t] += sh[t + o];
        __syncthreads();
    }
    if (t == 0) out[0] = sh[0] * (1.0f / (float)BB);
}

extern "C" void kernel_launch(void* const* d_in, const int* in_sizes, int n_in,
                              void* d_out, int out_size)
{
    const float* em    = (const float*)d_in[0];
    const int*   tags  = (const int*)d_in[1];
    const int*   masks = (const int*)d_in[2];
    const float* start = (const float*)d_in[3];
    const float* endt  = (const float*)d_in[4];
    const float* trans = (const float*)d_in[5];
    float* out = (float*)d_out;

    crf_forward_kernel<<<BB / TEAMS, FWD_THREADS>>>(em, masks, start, endt, trans);
    crf_num_kernel<<<BB, 128>>>(em, tags, masks, start, endt, trans);
    crf_reduce_kernel<<<1, BB>>>(out);
}